// round 1
// baseline (speedup 1.0000x reference)
#include <cuda_runtime.h>
#include <math.h>

#define BQ 10000
#define DD 64
#define MM 50
#define BB 64
#define TT 512
#define BT (BB*TT)          // 32768 rows
#define NW 192              // padded output cols for K1 (50 w | 64 e | 64 a | pad)
#define NROWS_OUT (BB*(TT-1))  // 32704

// ---------------- scratch (device globals; no allocation allowed) ----------
__device__ float g_w[BT*MM];            // w logits, then softmaxed in place
__device__ float g_e[BT*DD];            // erase gate
__device__ float g_a[BT*DD];            // add gate
__device__ float g_read[NROWS_OUT*DD];  // read vectors, row = b*(T-1)+ (t-1)
__device__ float g_Wt2[NW*DD];          // combined transposed weights for K1
__device__ float g_bias[NW];
__device__ float g_fWt[DD*2*DD];        // f_W transposed: [j][i], 64 x 128

// ---------------- K0: weight prep ------------------------------------------
__global__ void k0_prep(const float* __restrict__ Mk,
                        const float* __restrict__ eW,
                        const float* __restrict__ aW,
                        const float* __restrict__ eb,
                        const float* __restrict__ ab,
                        const float* __restrict__ fW) {
    int idx = blockIdx.x * blockDim.x + threadIdx.x;
    int stride = gridDim.x * blockDim.x;
    for (int p = idx; p < NW*DD; p += stride) {
        int j = p / DD, i = p % DD;
        float v = 0.f;
        if (j < 50)            v = Mk[j*DD + i];
        else if (j < 114)      v = eW[i*DD + (j-50)];
        else if (j < 178)      v = aW[i*DD + (j-114)];
        g_Wt2[p] = v;
    }
    for (int j = idx; j < NW; j += stride) {
        float bv = 0.f;
        if (j >= 50 && j < 114)        bv = eb[j-50];
        else if (j >= 114 && j < 178)  bv = ab[j-114];
        g_bias[j] = bv;
    }
    for (int p = idx; p < DD*2*DD; p += stride) {
        int j = p / (2*DD), i = p % (2*DD);
        g_fWt[p] = fW[i*DD + j];
    }
}

// ---------------- K1: w logits + e + a for all (b,t) rows -------------------
// 384 threads: thread = (j, s) with j = tid>>1 output col, s = tid&1 i-half.
// Weights live in registers (8 x float4). x staged in shared per row.
__global__ __launch_bounds__(384) void k1_wea(
    const int* __restrict__ question, const int* __restrict__ response,
    const float* __restrict__ k_emb,  const float* __restrict__ v_emb) {
    __shared__ __align__(16) float sx[128];   // [k(64) | v(64)]
    int tid = threadIdx.x;
    int j = tid >> 1, s = tid & 1;
    int rot = j & 7;

    float4 wq[8];
    const float4* W4 = (const float4*)(g_Wt2 + j*DD + s*32);
#pragma unroll
    for (int u = 0; u < 8; u++) wq[u] = W4[(u + rot) & 7];
    float bias = g_bias[j];
    int xq_base = ((j < 50) ? 0 : 16) + s*8;   // quad index into sx
    const float4* sx4 = (const float4*)sx;

    for (int r = blockIdx.x; r < BT; r += gridDim.x) {
        if (tid < 128) {
            int q = question[r];
            if (tid < 64) {
                sx[tid] = k_emb[q*DD + tid];
            } else {
                int xid = q + BQ * response[r];
                sx[tid] = v_emb[xid*DD + (tid - 64)];
            }
        }
        __syncthreads();

        float a0 = 0.f, a1 = 0.f;
#pragma unroll
        for (int u = 0; u < 8; u++) {
            int qi = (u + rot) & 7;
            float4 x = sx4[xq_base + qi];
            float4 w = wq[u];
            a0 = fmaf(x.x, w.x, a0); a1 = fmaf(x.y, w.y, a1);
            a0 = fmaf(x.z, w.z, a0); a1 = fmaf(x.w, w.w, a1);
        }
        float acc = a0 + a1;
        acc += __shfl_down_sync(0xffffffffu, acc, 1, 2);  // combine i-halves
        if (s == 0 && j < 178) {
            float v = acc + bias;
            if (j < 50)        g_w[r*MM + j] = v;                       // raw logit
            else if (j < 114)  g_e[r*DD + (j-50)]  = 1.f/(1.f + expf(-v));
            else               g_a[r*DD + (j-114)] = tanhf(v);
        }
        __syncthreads();
    }
}

// ---------------- K1b: softmax over M=50 (warp per row, in place) ----------
__global__ void k1b_softmax() {
    int gw   = (blockIdx.x * blockDim.x + threadIdx.x) >> 5;
    int lane = threadIdx.x & 31;
    int nwarps = (gridDim.x * blockDim.x) >> 5;
    for (int r = gw; r < BT; r += nwarps) {
        float v0 = g_w[r*MM + lane];
        float v1 = (lane + 32 < MM) ? g_w[r*MM + lane + 32] : -1e30f;
        float mx = fmaxf(v0, v1);
#pragma unroll
        for (int o = 16; o; o >>= 1) mx = fmaxf(mx, __shfl_xor_sync(0xffffffffu, mx, o));
        float e0 = expf(v0 - mx);
        float e1 = (lane + 32 < MM) ? expf(v1 - mx) : 0.f;
        float sm = e0 + e1;
#pragma unroll
        for (int o = 16; o; o >>= 1) sm += __shfl_xor_sync(0xffffffffu, sm, o);
        float inv = 1.f / sm;
        g_w[r*MM + lane] = e0 * inv;
        if (lane + 32 < MM) g_w[r*MM + lane + 32] = e1 * inv;
    }
}

// ---------------- K2: sequential recurrence over t --------------------------
// 128 blocks = (b, d-half). 128 threads = 16 d-pairs x 8 m-parts.
// Mv columns in registers; prefetch t+1; no __syncthreads in the loop.
__global__ __launch_bounds__(128) void k2_scan(const float* __restrict__ mask,
                                               const float* __restrict__ Mv0) {
    int b = blockIdx.x >> 1;
    int dbase = (blockIdx.x & 1) * 32;
    int tid = threadIdx.x;
    int dp = tid >> 3, mp = tid & 7;
    int d0 = dbase + dp*2, d1 = d0 + 1;

    float mv0[7], mv1[7];
#pragma unroll
    for (int jj = 0; jj < 7; jj++) {
        int m = mp + 8*jj;
        mv0[jj] = (m < MM) ? Mv0[m*DD + d0] : 0.f;
        mv1[jj] = (m < MM) ? Mv0[m*DD + d1] : 0.f;
    }

    const float* wb  = g_w + (size_t)b*TT*MM;
    const float* ebp = g_e + (size_t)b*TT*DD;
    const float* abp = g_a + (size_t)b*TT*DD;
    const float* mkb = mask + b*TT;
    float* rb = g_read + (size_t)b*(TT-1)*DD;

    // prefetch t = 0
    float w0[7], e0a, e0b, a0a, a0b, mk0;
#pragma unroll
    for (int jj = 0; jj < 7; jj++) {
        int m = mp + 8*jj;
        w0[jj] = (m < MM) ? wb[m] : 0.f;
    }
    e0a = ebp[d0]; e0b = ebp[d1];
    a0a = abp[d0]; a0b = abp[d1];
    mk0 = mkb[0];

    for (int t = 0; t < TT; t++) {
        // ---- prefetch t+1 (overlaps with compute below) ----
        float w1[7], e1a = 0.f, e1b = 0.f, a1a = 0.f, a1b = 0.f, mk1 = 0.f;
#pragma unroll
        for (int jj = 0; jj < 7; jj++) w1[jj] = 0.f;
        if (t + 1 < TT) {
            int bs = t + 1;
#pragma unroll
            for (int jj = 0; jj < 7; jj++) {
                int m = mp + 8*jj;
                w1[jj] = (m < MM) ? wb[bs*MM + m] : 0.f;
            }
            e1a = ebp[bs*DD + d0]; e1b = ebp[bs*DD + d1];
            a1a = abp[bs*DD + d0]; a1b = abp[bs*DD + d1];
            mk1 = mkb[bs];
        }

        // ---- read (uses state after step t-1 with w_t) ----
        if (t > 0) {
            float r0 = 0.f, r1 = 0.f;
#pragma unroll
            for (int jj = 0; jj < 7; jj++) {
                r0 = fmaf(w0[jj], mv0[jj], r0);
                r1 = fmaf(w0[jj], mv1[jj], r1);
            }
            r0 += __shfl_down_sync(0xffffffffu, r0, 4, 8);
            r0 += __shfl_down_sync(0xffffffffu, r0, 2, 8);
            r0 += __shfl_down_sync(0xffffffffu, r0, 1, 8);
            r1 += __shfl_down_sync(0xffffffffu, r1, 4, 8);
            r1 += __shfl_down_sync(0xffffffffu, r1, 2, 8);
            r1 += __shfl_down_sync(0xffffffffu, r1, 1, 8);
            if (mp == 0) {
                rb[(t-1)*DD + d0] = r0;
                rb[(t-1)*DD + d1] = r1;
            }
        }

        // ---- update: fold mask into e/a so update is unconditional ----
        float f  = (mk0 == 1.0f) ? 1.f : 0.f;
        float ea0 = e0a * f, ea1 = e0b * f;
        float aa0 = a0a * f, aa1 = a0b * f;
#pragma unroll
        for (int jj = 0; jj < 7; jj++) {
            float u0 = fmaf(-w0[jj], ea0, 1.f);
            float u1 = fmaf(-w0[jj], ea1, 1.f);
            mv0[jj] = fmaf(mv0[jj], u0, w0[jj]*aa0);
            mv1[jj] = fmaf(mv1[jj], u1, w0[jj]*aa1);
        }

        // rotate pipeline registers
#pragma unroll
        for (int jj = 0; jj < 7; jj++) w0[jj] = w1[jj];
        e0a = e1a; e0b = e1b; a0a = a1a; a0b = a1b; mk0 = mk1;
    }
}

// ---------------- K3: f = tanh([read,k] @ f_W + f_b); p = f @ p_W + p_b -----
// 256 threads: thread = (j, s) with j = tid>>2 output col, s = tid&3 i-quarter.
// f_W rows live in registers (8 x float4 per thread).
__global__ __launch_bounds__(256) void k3_out(
    const int* __restrict__ question, const float* __restrict__ k_emb,
    const float* __restrict__ f_b, const float* __restrict__ p_W,
    const float* __restrict__ p_b, float* __restrict__ out) {
    __shared__ __align__(16) float sc[128];   // [read(64) | k(64)]
    __shared__ float warp_ps[8];
    int tid = threadIdx.x;
    int j = tid >> 2, s = tid & 3;
    int rot = j & 7;
    int lane = tid & 31, wid = tid >> 5;

    float4 wq[8];
    const float4* W4 = (const float4*)(g_fWt + j*128 + s*32);
#pragma unroll
    for (int u = 0; u < 8; u++) wq[u] = W4[(u + rot) & 7];
    float fb = f_b[j], pw = p_W[j];
    float pbv = p_b[0];
    const float4* sc4 = (const float4*)sc;
    int cbase = s*8;

    for (int r = blockIdx.x; r < NROWS_OUT; r += gridDim.x) {
        int b = r / (TT-1), tt = r % (TT-1);
        if (tid < 128) {
            if (tid < 64) {
                sc[tid] = g_read[(size_t)r*DD + tid];
            } else {
                int q = question[b*TT + tt + 1];
                sc[tid] = k_emb[q*DD + (tid - 64)];
            }
        }
        __syncthreads();

        float a0 = 0.f, a1 = 0.f;
#pragma unroll
        for (int u = 0; u < 8; u++) {
            int qi = (u + rot) & 7;
            float4 x = sc4[cbase + qi];
            float4 w = wq[u];
            a0 = fmaf(x.x, w.x, a0); a1 = fmaf(x.y, w.y, a1);
            a0 = fmaf(x.z, w.z, a0); a1 = fmaf(x.w, w.w, a1);
        }
        float acc = a0 + a1;
        acc += __shfl_down_sync(0xffffffffu, acc, 2, 4);   // combine i-quarters
        acc += __shfl_down_sync(0xffffffffu, acc, 1, 4);
        float pv = 0.f;
        if (s == 0) pv = tanhf(acc + fb) * pw;
#pragma unroll
        for (int o = 16; o; o >>= 1) pv += __shfl_xor_sync(0xffffffffu, pv, o);
        if (lane == 0) warp_ps[wid] = pv;
        __syncthreads();
        if (tid == 0) {
            float sum = pbv;
#pragma unroll
            for (int wgi = 0; wgi < 8; wgi++) sum += warp_ps[wgi];
            out[r] = sum;
        }
        // next iteration's __syncthreads (after staging) protects warp_ps;
        // sc is only rewritten after all threads passed the sync above.
    }
}

// ---------------- launch ----------------------------------------------------
extern "C" void kernel_launch(void* const* d_in, const int* in_sizes, int n_in,
                              void* d_out, int out_size) {
    const int*   question = (const int*)  d_in[0];
    const int*   response = (const int*)  d_in[1];
    const float* mask     = (const float*)d_in[2];
    const float* k_emb    = (const float*)d_in[3];
    const float* v_emb    = (const float*)d_in[4];
    const float* Mk       = (const float*)d_in[5];
    const float* Mv0      = (const float*)d_in[6];
    const float* e_W      = (const float*)d_in[7];
    // e_b = d_in[8]
    const float* a_W      = (const float*)d_in[9];
    // a_b = d_in[10]
    const float* f_W      = (const float*)d_in[11];
    const float* f_b      = (const float*)d_in[12];
    const float* p_W      = (const float*)d_in[13];
    const float* p_b      = (const float*)d_in[14];
    const float* e_b      = (const float*)d_in[8];
    const float* a_b      = (const float*)d_in[10];
    float* out = (float*)d_out;

    k0_prep<<<64, 256>>>(Mk, e_W, a_W, e_b, a_b, f_W);
    k1_wea<<<296, 384>>>(question, response, k_emb, v_emb);
    k1b_softmax<<<128, 256>>>();
    k2_scan<<<128, 128>>>(mask, Mv0);
    k3_out<<<296, 256>>>(question, k_emb, f_b, p_W, p_b, out);
}

// round 2
// speedup vs baseline: 1.2283x; 1.2283x over previous
#include <cuda_runtime.h>
#include <math.h>

#define BQ 10000
#define DD 64
#define MM 50
#define BB 64
#define TT 512
#define BT (BB*TT)              // 32768 rows
#define NW 192                  // padded output cols for K1 (50 w | 64 e | 64 a | pad)
#define NROWS_OUT (BB*(TT-1))   // 32704
#define NCH 32                  // chunks over T
#define CHL 16                  // steps per chunk (NCH*CHL == TT)
#define MD (MM*DD)              // 3200

// ---------------- scratch (device globals; no allocation allowed) ----------
__device__ float g_w[BT*64];             // w logits -> softmaxed, padded to 64 (cols 50..63 = 0)
__device__ float g_e[BT*DD];             // erase gate
__device__ float g_a[BT*DD];             // add gate
__device__ float g_read[NROWS_OUT*DD];   // read vectors, row = b*(T-1)+(t-1)
__device__ float g_U[BB*NCH*MD];         // chunk-composed multiplier
__device__ float g_C[BB*NCH*MD];         // chunk-composed additive
__device__ float g_mvstart[BB*NCH*MD];   // Mv state at each chunk start
__device__ float g_Wt2[NW*DD];           // combined transposed weights for K1
__device__ float g_bias[NW];
__device__ float g_fWt[DD*2*DD];         // f_W transposed: [j][i], 64 x 128

// ---------------- K0: weight prep ------------------------------------------
__global__ void k0_prep(const float* __restrict__ Mk,
                        const float* __restrict__ eW,
                        const float* __restrict__ aW,
                        const float* __restrict__ eb,
                        const float* __restrict__ ab,
                        const float* __restrict__ fW) {
    int idx = blockIdx.x * blockDim.x + threadIdx.x;
    int stride = gridDim.x * blockDim.x;
    for (int p = idx; p < NW*DD; p += stride) {
        int j = p / DD, i = p % DD;
        float v = 0.f;
        if (j < 50)            v = Mk[j*DD + i];
        else if (j < 114)      v = eW[i*DD + (j-50)];
        else if (j < 178)      v = aW[i*DD + (j-114)];
        g_Wt2[p] = v;
    }
    for (int j = idx; j < NW; j += stride) {
        float bv = 0.f;
        if (j >= 50 && j < 114)        bv = eb[j-50];
        else if (j >= 114 && j < 178)  bv = ab[j-114];
        g_bias[j] = bv;
    }
    for (int p = idx; p < DD*2*DD; p += stride) {
        int j = p / (2*DD), i = p % (2*DD);
        g_fWt[p] = fW[i*DD + j];
    }
}

// ---------------- K1: w logits + e + a, 4 rows per barrier ------------------
#define RB1 4
__global__ __launch_bounds__(384) void k1_wea(
    const int* __restrict__ question, const int* __restrict__ response,
    const float* __restrict__ k_emb,  const float* __restrict__ v_emb) {
    __shared__ __align__(16) float sx[RB1][128];   // [k(64) | v(64)]
    int tid = threadIdx.x;
    int j = tid >> 1, s = tid & 1;
    int rot = j & 7;

    float4 wq[8];
    const float4* W4 = (const float4*)(g_Wt2 + j*DD + s*32);
#pragma unroll
    for (int u = 0; u < 8; u++) wq[u] = W4[(u + rot) & 7];
    float bias = g_bias[j];
    int xq_base = ((j < 50) ? 0 : 16) + s*8;   // quad index into a row of sx
    bool is_w = (j < 50), is_e = (j >= 50 && j < 114), is_a = (j >= 114 && j < 178);
    int wcol = j, ecol = j - 50, acol = j - 114;

    for (int r0 = blockIdx.x*RB1; r0 < BT; r0 += gridDim.x*RB1) {
        // stage 4 rows (BT divisible by grid*RB1 -> no guards)
        for (int i = tid; i < RB1*128; i += 384) {
            int rr = i >> 7, c = i & 127;
            int r = r0 + rr;
            int q = question[r];
            if (c < 64) sx[rr][c] = k_emb[q*DD + c];
            else        sx[rr][c] = v_emb[(q + BQ*response[r])*DD + (c - 64)];
        }
        __syncthreads();

        float acc0[RB1], acc1[RB1];
#pragma unroll
        for (int rr = 0; rr < RB1; rr++) { acc0[rr] = 0.f; acc1[rr] = 0.f; }
#pragma unroll
        for (int u = 0; u < 8; u++) {
            int qi = (u + rot) & 7;
            float4 w = wq[u];
#pragma unroll
            for (int rr = 0; rr < RB1; rr++) {
                float4 x = ((const float4*)sx[rr])[xq_base + qi];
                acc0[rr] = fmaf(x.x, w.x, acc0[rr]); acc1[rr] = fmaf(x.y, w.y, acc1[rr]);
                acc0[rr] = fmaf(x.z, w.z, acc0[rr]); acc1[rr] = fmaf(x.w, w.w, acc1[rr]);
            }
        }
#pragma unroll
        for (int rr = 0; rr < RB1; rr++) {
            float acc = acc0[rr] + acc1[rr];
            acc += __shfl_down_sync(0xffffffffu, acc, 1, 2);  // combine i-halves
            if (s == 0) {
                int r = r0 + rr;
                float v = acc + bias;
                if (is_w)      g_w[(size_t)r*64 + wcol] = v;   // raw logit (padded row)
                else if (is_e) g_e[(size_t)r*DD + ecol] = 1.f/(1.f + expf(-v));
                else if (is_a) g_a[(size_t)r*DD + acol] = tanhf(v);
            }
        }
        __syncthreads();
    }
}

// ---------------- K1b: softmax over M=50 (warp/row), writes padded 64 ------
__global__ void k1b_softmax() {
    int gw   = (blockIdx.x * blockDim.x + threadIdx.x) >> 5;
    int lane = threadIdx.x & 31;
    int nwarps = (gridDim.x * blockDim.x) >> 5;
    for (int r = gw; r < BT; r += nwarps) {
        const size_t base = (size_t)r * 64;
        float v0 = g_w[base + lane];
        float v1 = (lane + 32 < MM) ? g_w[base + lane + 32] : -1e30f;
        float mx = fmaxf(v0, v1);
#pragma unroll
        for (int o = 16; o; o >>= 1) mx = fmaxf(mx, __shfl_xor_sync(0xffffffffu, mx, o));
        float e0 = expf(v0 - mx);
        float e1 = (lane + 32 < MM) ? expf(v1 - mx) : 0.f;
        float sm = e0 + e1;
#pragma unroll
        for (int o = 16; o; o >>= 1) sm += __shfl_xor_sync(0xffffffffu, sm, o);
        float inv = 1.f / sm;
        g_w[base + lane] = e0 * inv;
        g_w[base + lane + 32] = (lane + 32 < MM) ? e1 * inv : 0.f;  // zero pad
    }
}

// ---------------- K2a: per-chunk composed linear-recurrence coefficients ----
// block = (b, chunk). 256 threads = 32 d-pairs x 8 m-parts.
// Recurrence per (m,d): Mv' = u*Mv + c, u = 1 - w*e*f, c = w*a*f.
__global__ __launch_bounds__(256) void k2a(const float* __restrict__ mask) {
    int blk = blockIdx.x;
    int b = blk >> 5, c = blk & (NCH-1);
    int tid = threadIdx.x;
    int dp = tid >> 3, mp = tid & 7;
    int d0 = dp*2, d1 = d0 + 1;

    const float* wb  = g_w + ((size_t)b*TT + c*CHL)*64;
    const float* ebp = g_e + ((size_t)b*TT + c*CHL)*DD;
    const float* abp = g_a + ((size_t)b*TT + c*CHL)*DD;
    const float* mkb = mask + b*TT + c*CHL;

    float U0[7], U1[7], C0[7], C1[7];
#pragma unroll
    for (int jj = 0; jj < 7; jj++) { U0[jj]=1.f; U1[jj]=1.f; C0[jj]=0.f; C1[jj]=0.f; }

#pragma unroll 4
    for (int s = 0; s < CHL; s++) {
        float f = (mkb[s] == 1.0f) ? 1.f : 0.f;
        float e0 = ebp[s*DD + d0]*f, e1 = ebp[s*DD + d1]*f;
        float a0 = abp[s*DD + d0]*f, a1 = abp[s*DD + d1]*f;
#pragma unroll
        for (int jj = 0; jj < 7; jj++) {
            float w = wb[s*64 + mp + 8*jj];   // padded: w==0 for m>=50 -> identity
            float u0 = fmaf(-w, e0, 1.f);
            float u1 = fmaf(-w, e1, 1.f);
            U0[jj] *= u0;  U1[jj] *= u1;
            C0[jj] = fmaf(C0[jj], u0, w*a0);
            C1[jj] = fmaf(C1[jj], u1, w*a1);
        }
    }
    size_t off = (size_t)(b*NCH + c) * MD;
#pragma unroll
    for (int jj = 0; jj < 7; jj++) {
        int m = mp + 8*jj;
        if (m < MM) {
            g_U[off + m*DD + d0] = U0[jj];  g_U[off + m*DD + d1] = U1[jj];
            g_C[off + m*DD + d0] = C0[jj];  g_C[off + m*DD + d1] = C1[jj];
        }
    }
}

// ---------------- K2b: compose chunk aggregates -> chunk start states -------
__global__ __launch_bounds__(256) void k2b(const float* __restrict__ Mv0) {
    int idx = blockIdx.x * blockDim.x + threadIdx.x;   // 0 .. BB*MD-1
    if (idx >= BB*MD) return;
    int b = idx / MD, md = idx % MD;
    float mv = Mv0[md];
#pragma unroll 4
    for (int c = 0; c < NCH; c++) {
        size_t off = (size_t)(b*NCH + c) * MD + md;
        g_mvstart[off] = mv;
        mv = fmaf(mv, g_U[off], g_C[off]);
    }
}

// ---------------- K2c: replay chunks, emit read vectors ---------------------
__global__ __launch_bounds__(256) void k2c(const float* __restrict__ mask) {
    int blk = blockIdx.x;
    int b = blk >> 5, c = blk & (NCH-1);
    int tid = threadIdx.x;
    int dp = tid >> 3, mp = tid & 7;
    int d0 = dp*2, d1 = d0 + 1;

    const float* wb  = g_w + ((size_t)b*TT + c*CHL)*64;
    const float* ebp = g_e + ((size_t)b*TT + c*CHL)*DD;
    const float* abp = g_a + ((size_t)b*TT + c*CHL)*DD;
    const float* mkb = mask + b*TT + c*CHL;
    float* rb = g_read + (size_t)b*(TT-1)*DD;

    size_t soff = (size_t)(b*NCH + c) * MD;
    float mv0[7], mv1[7];
#pragma unroll
    for (int jj = 0; jj < 7; jj++) {
        int m = mp + 8*jj;
        mv0[jj] = (m < MM) ? g_mvstart[soff + m*DD + d0] : 0.f;
        mv1[jj] = (m < MM) ? g_mvstart[soff + m*DD + d1] : 0.f;
    }

#pragma unroll 2
    for (int s = 0; s < CHL; s++) {
        int t = c*CHL + s;
        float w[7];
#pragma unroll
        for (int jj = 0; jj < 7; jj++) w[jj] = wb[s*64 + mp + 8*jj];
        float f = (mkb[s] == 1.0f) ? 1.f : 0.f;
        float e0 = ebp[s*DD + d0]*f, e1 = ebp[s*DD + d1]*f;
        float a0 = abp[s*DD + d0]*f, a1 = abp[s*DD + d1]*f;

        if (t > 0) {   // read with w_t against state after t-1
            float r0 = 0.f, r1 = 0.f;
#pragma unroll
            for (int jj = 0; jj < 7; jj++) {
                r0 = fmaf(w[jj], mv0[jj], r0);
                r1 = fmaf(w[jj], mv1[jj], r1);
            }
            r0 += __shfl_down_sync(0xffffffffu, r0, 4, 8);
            r0 += __shfl_down_sync(0xffffffffu, r0, 2, 8);
            r0 += __shfl_down_sync(0xffffffffu, r0, 1, 8);
            r1 += __shfl_down_sync(0xffffffffu, r1, 4, 8);
            r1 += __shfl_down_sync(0xffffffffu, r1, 2, 8);
            r1 += __shfl_down_sync(0xffffffffu, r1, 1, 8);
            if (mp == 0) {
                rb[(size_t)(t-1)*DD + d0] = r0;
                rb[(size_t)(t-1)*DD + d1] = r1;
            }
        }
#pragma unroll
        for (int jj = 0; jj < 7; jj++) {
            float u0 = fmaf(-w[jj], e0, 1.f);
            float u1 = fmaf(-w[jj], e1, 1.f);
            mv0[jj] = fmaf(mv0[jj], u0, w[jj]*a0);
            mv1[jj] = fmaf(mv1[jj], u1, w[jj]*a1);
        }
    }
}

// ---------------- K3: f = tanh([read,k] @ f_W + f_b); p = f @ p_W + p_b -----
#define RB3 4
__global__ __launch_bounds__(256) void k3_out(
    const int* __restrict__ question, const float* __restrict__ k_emb,
    const float* __restrict__ f_b, const float* __restrict__ p_W,
    const float* __restrict__ p_b, float* __restrict__ out) {
    __shared__ __align__(16) float sc[RB3][128];   // [read(64) | k(64)]
    __shared__ float warp_ps[8][RB3];
    int tid = threadIdx.x;
    int j = tid >> 2, s = tid & 3;
    int rot = j & 7;
    int lane = tid & 31, wid = tid >> 5;

    float4 wq[8];
    const float4* W4 = (const float4*)(g_fWt + j*128 + s*32);
#pragma unroll
    for (int u = 0; u < 8; u++) wq[u] = W4[(u + rot) & 7];
    float fb = f_b[j], pw = p_W[j];
    float pbv = p_b[0];
    int cbase = s*8;

    for (int r0 = blockIdx.x*RB3; r0 < NROWS_OUT; r0 += gridDim.x*RB3) {
        for (int i = tid; i < RB3*128; i += 256) {
            int rr = i >> 7, cc = i & 127;
            int r = r0 + rr;
            if (r < NROWS_OUT) {
                if (cc < 64) sc[rr][cc] = g_read[(size_t)r*DD + cc];
                else {
                    int bb = r / (TT-1), ttt = r % (TT-1);
                    sc[rr][cc] = k_emb[(size_t)question[bb*TT + ttt + 1]*DD + (cc - 64)];
                }
            }
        }
        __syncthreads();

        float acc0[RB3], acc1[RB3];
#pragma unroll
        for (int rr = 0; rr < RB3; rr++) { acc0[rr]=0.f; acc1[rr]=0.f; }
#pragma unroll
        for (int u = 0; u < 8; u++) {
            int qi = (u + rot) & 7;
            float4 w = wq[u];
#pragma unroll
            for (int rr = 0; rr < RB3; rr++) {
                float4 x = ((const float4*)sc[rr])[cbase + qi];
                acc0[rr] = fmaf(x.x, w.x, acc0[rr]); acc1[rr] = fmaf(x.y, w.y, acc1[rr]);
                acc0[rr] = fmaf(x.z, w.z, acc0[rr]); acc1[rr] = fmaf(x.w, w.w, acc1[rr]);
            }
        }
#pragma unroll
        for (int rr = 0; rr < RB3; rr++) {
            float acc = acc0[rr] + acc1[rr];
            acc += __shfl_down_sync(0xffffffffu, acc, 2, 4);
            acc += __shfl_down_sync(0xffffffffu, acc, 1, 4);
            float pv = (s == 0) ? tanhf(acc + fb) * pw : 0.f;
#pragma unroll
            for (int o = 16; o; o >>= 1) pv += __shfl_xor_sync(0xffffffffu, pv, o);
            if (lane == 0) warp_ps[wid][rr] = pv;
        }
        __syncthreads();
        if (tid < RB3) {
            int r = r0 + tid;
            if (r < NROWS_OUT) {
                float sum = pbv;
#pragma unroll
                for (int wgi = 0; wgi < 8; wgi++) sum += warp_ps[wgi][tid];
                out[r] = sum;
            }
        }
        __syncthreads();
    }
}

// ---------------- launch ----------------------------------------------------
extern "C" void kernel_launch(void* const* d_in, const int* in_sizes, int n_in,
                              void* d_out, int out_size) {
    const int*   question = (const int*)  d_in[0];
    const int*   response = (const int*)  d_in[1];
    const float* mask     = (const float*)d_in[2];
    const float* k_emb    = (const float*)d_in[3];
    const float* v_emb    = (const float*)d_in[4];
    const float* Mk       = (const float*)d_in[5];
    const float* Mv0      = (const float*)d_in[6];
    const float* e_W      = (const float*)d_in[7];
    const float* e_b      = (const float*)d_in[8];
    const float* a_W      = (const float*)d_in[9];
    const float* a_b      = (const float*)d_in[10];
    const float* f_W      = (const float*)d_in[11];
    const float* f_b      = (const float*)d_in[12];
    const float* p_W      = (const float*)d_in[13];
    const float* p_b      = (const float*)d_in[14];
    float* out = (float*)d_out;

    k0_prep<<<64, 256>>>(Mk, e_W, a_W, e_b, a_b, f_W);
    k1_wea<<<1024, 384>>>(question, response, k_emb, v_emb);
    k1b_softmax<<<256, 256>>>();
    k2a<<<BB*NCH, 256>>>(mask);
    k2b<<<(BB*MD + 255)/256, 256>>>(Mv0);
    k2c<<<BB*NCH, 256>>>(mask);
    k3_out<<<1024, 256>>>(question, k_emb, f_b, p_W, p_b, out);
}

// round 3
// speedup vs baseline: 1.8240x; 1.4850x over previous
#include <cuda_runtime.h>
#include <math.h>

#define BQ 10000
#define DD 64
#define MM 50
#define BB 64
#define TT 512
#define BT (BB*TT)              // 32768 rows
#define NW 192                  // padded weight rows for K1 (50 w | 64 e | 64 a | pad)
#define NROWS_OUT (BB*(TT-1))   // 32704
#define NCH 32                  // chunks over T
#define CHL 16                  // steps per chunk (NCH*CHL == TT)
#define MD (MM*DD)              // 3200

// ---------------- scratch (device globals; no allocation allowed) ----------
__device__ float g_w[BT*64];             // softmaxed w, PERMUTED cols: slot=(m&7)*8+(m>>3), pad 0
__device__ float g_e[BT*DD];             // erase gate * maskflag
__device__ float g_a[BT*DD];             // add gate * maskflag
__device__ float g_read[NROWS_OUT*DD];   // read vectors, row = b*(T-1)+(t-1)
__device__ float g_UC[BB*NCH*MD*2];      // interleaved (U,C) chunk aggregates
__device__ float g_mvstart[BB*NCH*MD];   // Mv state at each chunk start
__device__ float g_Wt2[NW*DD];           // combined weights for K1: row j = output col
__device__ float g_bias[NW];
__device__ float g_fWt[DD*2*DD];         // f_W transposed: [j][i], 64 x 128

// ---------------- K0: weight prep ------------------------------------------
__global__ void k0_prep(const float* __restrict__ Mk,
                        const float* __restrict__ eW,
                        const float* __restrict__ aW,
                        const float* __restrict__ eb,
                        const float* __restrict__ ab,
                        const float* __restrict__ fW) {
    int idx = blockIdx.x * blockDim.x + threadIdx.x;
    int stride = gridDim.x * blockDim.x;
    for (int p = idx; p < NW*DD; p += stride) {
        int j = p / DD, i = p % DD;
        float v = 0.f;
        if (j < 50)            v = Mk[j*DD + i];
        else if (j < 114)      v = eW[i*DD + (j-50)];
        else if (j < 178)      v = aW[i*DD + (j-114)];
        g_Wt2[p] = v;
    }
    for (int j = idx; j < NW; j += stride) {
        float bv = 0.f;
        if (j >= 50 && j < 114)        bv = eb[j-50];
        else if (j >= 114 && j < 178)  bv = ab[j-114];
        g_bias[j] = bv;
    }
    for (int p = idx; p < DD*2*DD; p += stride) {
        int j = p / (2*DD), i = p % (2*DD);
        g_fWt[p] = fW[i*DD + j];
    }
}

// ---------------- K1: w(+softmax,permuted) + e + a, fused, 4 rows/iter ------
// 192 threads, thread j = output col; 64 weights in registers (16 x float4).
// Shared-x reads are warp-uniform -> LDS broadcasts.
#define RB1 4
__global__ __launch_bounds__(192) void k1_wea(
    const int* __restrict__ question, const int* __restrict__ response,
    const float* __restrict__ mask,
    const float* __restrict__ k_emb,  const float* __restrict__ v_emb) {
    __shared__ __align__(16) float sx[RB1][128];   // per row: [k(64) | v(64)]
    __shared__ float slog[RB1][52];                // raw w logits
    int tid = threadIdx.x;
    int j = tid;
    int lane = tid & 31, wid = tid >> 5;

    float4 wq[16];
    const float4* W4 = (const float4*)(g_Wt2 + j*DD);
#pragma unroll
    for (int u = 0; u < 16; u++) wq[u] = W4[u];
    float bias = g_bias[j];
    int qbase = (j < 50) ? 0 : 16;     // k-half for w, v-half for e/a
    bool is_w = (j < 50), is_e = (j >= 50 && j < 114), is_a = (j >= 114 && j < 178);
    int ecol = j - 50, acol = j - 114;

    for (int r0 = blockIdx.x*RB1; r0 < BT; r0 += gridDim.x*RB1) {
        // stage 4 rows of [k|v] as float4s (128 f4, first 128 threads)
        if (tid < 128) {
            int rr = tid >> 5, q4 = tid & 31;
            int r = r0 + rr;
            int q = question[r];
            if (q4 < 16) ((float4*)sx[rr])[q4] = ((const float4*)k_emb)[q*16 + q4];
            else ((float4*)sx[rr])[q4] =
                ((const float4*)v_emb)[(q + BQ*response[r])*16 + (q4 - 16)];
        }
        __syncthreads();

        float acc[RB1];
#pragma unroll
        for (int rr = 0; rr < RB1; rr++) acc[rr] = 0.f;
#pragma unroll
        for (int u = 0; u < 16; u++) {
            float4 w = wq[u];
#pragma unroll
            for (int rr = 0; rr < RB1; rr++) {
                float4 x = ((const float4*)sx[rr])[qbase + u];   // warp-uniform-ish -> broadcast
                acc[rr] = fmaf(x.x, w.x, acc[rr]);
                acc[rr] = fmaf(x.y, w.y, acc[rr]);
                acc[rr] = fmaf(x.z, w.z, acc[rr]);
                acc[rr] = fmaf(x.w, w.w, acc[rr]);
            }
        }
#pragma unroll
        for (int rr = 0; rr < RB1; rr++) {
            float v = acc[rr] + bias;
            int r = r0 + rr;
            if (is_w) slog[rr][j] = v;
            else if (is_e || is_a) {
                float mk = (mask[r] == 1.0f) ? 1.f : 0.f;
                if (is_e) g_e[(size_t)r*DD + ecol] = mk / (1.f + expf(-v));
                else      g_a[(size_t)r*DD + acol] = mk * tanhf(v);
            }
        }
        __syncthreads();

        // softmax: warp rr handles row rr (50 logits), writes permuted + padded
        if (wid < RB1) {
            int rr = wid;
            size_t base = (size_t)(r0 + rr) * 64;
            float v0 = slog[rr][lane];
            float v1 = (lane < 18) ? slog[rr][lane + 32] : -1e30f;
            float mx = fmaxf(v0, v1);
#pragma unroll
            for (int o = 16; o; o >>= 1) mx = fmaxf(mx, __shfl_xor_sync(0xffffffffu, mx, o));
            float e0 = expf(v0 - mx);
            float e1 = (lane < 18) ? expf(v1 - mx) : 0.f;
            float sm = e0 + e1;
#pragma unroll
            for (int o = 16; o; o >>= 1) sm += __shfl_xor_sync(0xffffffffu, sm, o);
            float inv = 1.f / sm;
            int m0 = lane, m1 = lane + 32;
            g_w[base + ((m0 & 7)*8 + (m0 >> 3))] = e0 * inv;
            g_w[base + ((m1 & 7)*8 + (m1 >> 3))] = (lane < 18) ? e1 * inv : 0.f;
        }
        __syncthreads();
    }
}

// ---------------- K2a: per-chunk composed linear-recurrence coefficients ----
// block = (b, chunk). 256 threads = 32 d-pairs x 8 m-parts.
// per (m,d): Mv' = u*Mv + c, u = 1 - w*e, c = w*a   (mask pre-folded into e,a)
__global__ __launch_bounds__(256) void k2a() {
    int blk = blockIdx.x;
    int b = blk >> 5, c = blk & (NCH-1);
    int tid = threadIdx.x;
    int dp = tid >> 3, mp = tid & 7;
    int d0 = dp*2;

    const float* wb  = g_w + ((size_t)b*TT + c*CHL)*64 + mp*8;
    const float2* ebp = (const float2*)(g_e + ((size_t)b*TT + c*CHL)*DD + d0);
    const float2* abp = (const float2*)(g_a + ((size_t)b*TT + c*CHL)*DD + d0);

    float U0[7], U1[7], C0[7], C1[7];
#pragma unroll
    for (int jj = 0; jj < 7; jj++) { U0[jj]=1.f; U1[jj]=1.f; C0[jj]=0.f; C1[jj]=0.f; }

#pragma unroll 4
    for (int s = 0; s < CHL; s++) {
        float w[7];
        float4 w03 = *(const float4*)(wb + s*64);
        float2 w45 = *(const float2*)(wb + s*64 + 4);
        w[0]=w03.x; w[1]=w03.y; w[2]=w03.z; w[3]=w03.w;
        w[4]=w45.x; w[5]=w45.y; w[6]=wb[s*64 + 6];
        float2 e = ebp[s*32];
        float2 a = abp[s*32];
#pragma unroll
        for (int jj = 0; jj < 7; jj++) {
            float u0 = fmaf(-w[jj], e.x, 1.f);
            float u1 = fmaf(-w[jj], e.y, 1.f);
            U0[jj] *= u0;  U1[jj] *= u1;
            C0[jj] = fmaf(C0[jj], u0, w[jj]*a.x);
            C1[jj] = fmaf(C1[jj], u1, w[jj]*a.y);
        }
    }
    size_t off = (size_t)(b*NCH + c) * MD;
#pragma unroll
    for (int jj = 0; jj < 7; jj++) {
        int m = 8*jj + mp;
        if (m < MM) {
            // interleaved (U,C) pairs for d0,d1 -> one float4 store
            float4 v = make_float4(U0[jj], C0[jj], U1[jj], C1[jj]);
            *(float4*)(g_UC + (off + (size_t)m*DD + d0)*2) = v;
        }
    }
}

// ---------------- K2b: compose chunk aggregates -> chunk start states -------
__global__ __launch_bounds__(256) void k2b(const float* __restrict__ Mv0) {
    int idx = blockIdx.x * blockDim.x + threadIdx.x;   // 0 .. BB*MD-1
    if (idx >= BB*MD) return;
    int b = idx / MD, md = idx % MD;
    float mv = Mv0[md];
#pragma unroll 8
    for (int c = 0; c < NCH; c++) {
        size_t off = (size_t)(b*NCH + c) * MD + md;
        g_mvstart[off] = mv;
        float2 uc = *(const float2*)(g_UC + off*2);
        mv = fmaf(mv, uc.x, uc.y);
    }
}

// ---------------- K2c: replay chunks, emit read vectors ---------------------
__global__ __launch_bounds__(256) void k2c() {
    int blk = blockIdx.x;
    int b = blk >> 5, c = blk & (NCH-1);
    int tid = threadIdx.x;
    int dp = tid >> 3, mp = tid & 7;
    int d0 = dp*2, d1 = d0 + 1;

    const float* wb  = g_w + ((size_t)b*TT + c*CHL)*64 + mp*8;
    const float2* ebp = (const float2*)(g_e + ((size_t)b*TT + c*CHL)*DD + d0);
    const float2* abp = (const float2*)(g_a + ((size_t)b*TT + c*CHL)*DD + d0);
    float* rb = g_read + (size_t)b*(TT-1)*DD;

    size_t soff = (size_t)(b*NCH + c) * MD;
    float mv0[7], mv1[7];
#pragma unroll
    for (int jj = 0; jj < 7; jj++) {
        int m = 8*jj + mp;
        mv0[jj] = (m < MM) ? g_mvstart[soff + (size_t)m*DD + d0] : 0.f;
        mv1[jj] = (m < MM) ? g_mvstart[soff + (size_t)m*DD + d1] : 0.f;
    }

#pragma unroll 2
    for (int s = 0; s < CHL; s++) {
        int t = c*CHL + s;
        float w[7];
        float4 w03 = *(const float4*)(wb + s*64);
        float2 w45 = *(const float2*)(wb + s*64 + 4);
        w[0]=w03.x; w[1]=w03.y; w[2]=w03.z; w[3]=w03.w;
        w[4]=w45.x; w[5]=w45.y; w[6]=wb[s*64 + 6];
        float2 e = ebp[s*32];
        float2 a = abp[s*32];

        if (t > 0) {   // read with w_t against state after t-1
            float r0 = 0.f, r1 = 0.f;
#pragma unroll
            for (int jj = 0; jj < 7; jj++) {
                r0 = fmaf(w[jj], mv0[jj], r0);
                r1 = fmaf(w[jj], mv1[jj], r1);
            }
            r0 += __shfl_down_sync(0xffffffffu, r0, 4, 8);
            r0 += __shfl_down_sync(0xffffffffu, r0, 2, 8);
            r0 += __shfl_down_sync(0xffffffffu, r0, 1, 8);
            r1 += __shfl_down_sync(0xffffffffu, r1, 4, 8);
            r1 += __shfl_down_sync(0xffffffffu, r1, 2, 8);
            r1 += __shfl_down_sync(0xffffffffu, r1, 1, 8);
            if (mp == 0) {
                rb[(size_t)(t-1)*DD + d0] = r0;
                rb[(size_t)(t-1)*DD + d1] = r1;
            }
        }
#pragma unroll
        for (int jj = 0; jj < 7; jj++) {
            float u0 = fmaf(-w[jj], e.x, 1.f);
            float u1 = fmaf(-w[jj], e.y, 1.f);
            mv0[jj] = fmaf(mv0[jj], u0, w[jj]*a.x);
            mv1[jj] = fmaf(mv1[jj], u1, w[jj]*a.y);
        }
    }
}

// ---------------- K3: f = tanh([read,k] @ f_W + f_b); p = f @ p_W + p_b -----
// 128 threads: j = tid>>1, s = tid&1 (i-half). 64 weights in registers.
#define RB3 4
__global__ __launch_bounds__(128) void k3_out(
    const int* __restrict__ question, const float* __restrict__ k_emb,
    const float* __restrict__ f_b, const float* __restrict__ p_W,
    const float* __restrict__ p_b, float* __restrict__ out) {
    __shared__ __align__(16) float sc[RB3][128];   // [read(64) | k(64)]
    __shared__ float warp_ps[4][RB3];
    int tid = threadIdx.x;
    int j = tid >> 1, s = tid & 1;
    int lane = tid & 31, wid = tid >> 5;

    float4 wq[16];
    const float4* W4 = (const float4*)(g_fWt + j*128 + s*64);
#pragma unroll
    for (int u = 0; u < 16; u++) wq[u] = W4[u];
    float fb = f_b[j], pw = p_W[j];
    float pbv = p_b[0];
    int qbase = s*16;

    for (int r0 = blockIdx.x*RB3; r0 < NROWS_OUT; r0 += gridDim.x*RB3) {
        // stage: 128 threads = 4 rows x 32 quads
        {
            int rr = tid >> 5, q4 = tid & 31;
            int r = r0 + rr;
            if (r < NROWS_OUT) {
                if (q4 < 16) ((float4*)sc[rr])[q4] = ((const float4*)g_read)[(size_t)r*16 + q4];
                else {
                    int bb = r / (TT-1), ttt = r - bb*(TT-1);
                    int q = question[bb*TT + ttt + 1];
                    ((float4*)sc[rr])[q4] = ((const float4*)k_emb)[q*16 + (q4 - 16)];
                }
            }
        }
        __syncthreads();

        float acc[RB3];
#pragma unroll
        for (int rr = 0; rr < RB3; rr++) acc[rr] = 0.f;
#pragma unroll
        for (int u = 0; u < 16; u++) {
            float4 w = wq[u];
#pragma unroll
            for (int rr = 0; rr < RB3; rr++) {
                float4 x = ((const float4*)sc[rr])[qbase + u];
                acc[rr] = fmaf(x.x, w.x, acc[rr]);
                acc[rr] = fmaf(x.y, w.y, acc[rr]);
                acc[rr] = fmaf(x.z, w.z, acc[rr]);
                acc[rr] = fmaf(x.w, w.w, acc[rr]);
            }
        }
#pragma unroll
        for (int rr = 0; rr < RB3; rr++) {
            float a2 = acc[rr] + __shfl_down_sync(0xffffffffu, acc[rr], 1, 2);
            float pv = (s == 0) ? tanhf(a2 + fb) * pw : 0.f;
#pragma unroll
            for (int o = 16; o; o >>= 1) pv += __shfl_xor_sync(0xffffffffu, pv, o);
            if (lane == 0) warp_ps[wid][rr] = pv;
        }
        __syncthreads();
        if (tid < RB3) {
            int r = r0 + tid;
            if (r < NROWS_OUT) {
                float sum = pbv;
#pragma unroll
                for (int wgi = 0; wgi < 4; wgi++) sum += warp_ps[wgi][tid];
                out[r] = sum;
            }
        }
        __syncthreads();
    }
}

// ---------------- launch ----------------------------------------------------
extern "C" void kernel_launch(void* const* d_in, const int* in_sizes, int n_in,
                              void* d_out, int out_size) {
    const int*   question = (const int*)  d_in[0];
    const int*   response = (const int*)  d_in[1];
    const float* mask     = (const float*)d_in[2];
    const float* k_emb    = (const float*)d_in[3];
    const float* v_emb    = (const float*)d_in[4];
    const float* Mk       = (const float*)d_in[5];
    const float* Mv0      = (const float*)d_in[6];
    const float* e_W      = (const float*)d_in[7];
    const float* e_b      = (const float*)d_in[8];
    const float* a_W      = (const float*)d_in[9];
    const float* a_b      = (const float*)d_in[10];
    const float* f_W      = (const float*)d_in[11];
    const float* f_b      = (const float*)d_in[12];
    const float* p_W      = (const float*)d_in[13];
    const float* p_b      = (const float*)d_in[14];
    float* out = (float*)d_out;

    k0_prep<<<64, 256>>>(Mk, e_W, a_W, e_b, a_b, f_W);
    k1_wea<<<1024, 192>>>(question, response, mask, k_emb, v_emb);
    k2a<<<BB*NCH, 256>>>();
    k2b<<<(BB*MD + 255)/256, 256>>>(Mv0);
    k2c<<<BB*NCH, 256>>>();
    k3_out<<<1024, 128>>>(question, k_emb, f_b, p_W, p_b, out);
}

// round 4
// speedup vs baseline: 2.3438x; 1.2849x over previous
#include <cuda_runtime.h>
#include <math.h>

#define BQ 10000
#define DD 64
#define MM 50
#define BB 64
#define TT 512
#define BT (BB*TT)              // 32768 rows
#define NW 192                  // padded weight rows for K1 (50 w | 64 e | 64 a | pad)
#define NROWS_OUT (BB*(TT-1))   // 32704
#define NCH 16                  // chunks over T
#define CHL 32                  // steps per chunk (NCH*CHL == TT)
#define MD (MM*DD)              // 3200

// ---------------- scratch (device globals; no allocation allowed) ----------
__device__ float g_w[BT*64];             // softmaxed w, PERMUTED: slot=(m&7)*8+(m>>3), pads 0
__device__ float g_ea[BT*128];           // interleaved (e_d0,e_d1,a_d0,a_d1) per d-pair, mask folded
__device__ float g_read[NROWS_OUT*DD];   // read vectors, row = b*(T-1)+(t-1)
__device__ float g_UC[BB*NCH*MD*2];      // interleaved (U0,C0,U1,C1) chunk aggregates
__device__ float g_mvstart[BB*NCH*MD];   // Mv state at each chunk start
__device__ float g_Wt2[NW*DD];           // combined weights for K1: row j = output col
__device__ float g_bias[NW];
__device__ float g_fWt[DD*2*DD];         // f_W transposed: [j][i], 64 x 128

// ---------------- K0: weight prep ------------------------------------------
__global__ void k0_prep(const float* __restrict__ Mk,
                        const float* __restrict__ eW,
                        const float* __restrict__ aW,
                        const float* __restrict__ eb,
                        const float* __restrict__ ab,
                        const float* __restrict__ fW) {
    int idx = blockIdx.x * blockDim.x + threadIdx.x;
    int stride = gridDim.x * blockDim.x;
    for (int p = idx; p < NW*DD; p += stride) {
        int j = p / DD, i = p % DD;
        float v = 0.f;
        if (j < 50)            v = Mk[j*DD + i];
        else if (j < 114)      v = eW[i*DD + (j-50)];
        else if (j < 178)      v = aW[i*DD + (j-114)];
        g_Wt2[p] = v;
    }
    for (int j = idx; j < NW; j += stride) {
        float bv = 0.f;
        if (j >= 50 && j < 114)        bv = eb[j-50];
        else if (j >= 114 && j < 178)  bv = ab[j-114];
        g_bias[j] = bv;
    }
    for (int p = idx; p < DD*2*DD; p += stride) {
        int j = p / (2*DD), i = p % (2*DD);
        g_fWt[p] = fW[i*DD + j];
    }
}

// ---------------- K1: w(+softmax,permuted) + e/a (interleaved), 8 rows/iter -
// 192 threads, thread j = output col; 64 weights in registers (16 x float4).
#define RB1 8
__global__ __launch_bounds__(192) void k1_wea(
    const int* __restrict__ question, const int* __restrict__ response,
    const float* __restrict__ mask,
    const float* __restrict__ k_emb,  const float* __restrict__ v_emb) {
    __shared__ __align__(16) float sx[RB1][128];   // per row: [k(64) | v(64)]
    __shared__ float slog[RB1][52];                // raw w logits
    int tid = threadIdx.x;
    int j = tid;
    int lane = tid & 31, wid = tid >> 5;

    float4 wq[16];
    const float4* W4 = (const float4*)(g_Wt2 + j*DD);
#pragma unroll
    for (int u = 0; u < 16; u++) wq[u] = W4[u];
    float bias = g_bias[j];
    int qbase = (j < 50) ? 0 : 16;     // k-half for w, v-half for e/a
    bool is_w = (j < 50), is_e = (j >= 50 && j < 114), is_a = (j >= 114 && j < 178);
    int ecol = j - 50, acol = j - 114;

    for (int r0 = blockIdx.x*RB1; r0 < BT; r0 += gridDim.x*RB1) {
        // stage 8 rows of [k|v] as float4s (256 f4 over 192 threads)
        for (int i = tid; i < RB1*32; i += 192) {
            int rr = i >> 5, q4 = i & 31;
            int r = r0 + rr;
            int q = question[r];
            if (q4 < 16) ((float4*)sx[rr])[q4] = ((const float4*)k_emb)[q*16 + q4];
            else ((float4*)sx[rr])[q4] =
                ((const float4*)v_emb)[(q + BQ*response[r])*16 + (q4 - 16)];
        }
        __syncthreads();

        float acc[RB1];
#pragma unroll
        for (int rr = 0; rr < RB1; rr++) acc[rr] = 0.f;
#pragma unroll
        for (int u = 0; u < 16; u++) {
            float4 w = wq[u];
#pragma unroll
            for (int rr = 0; rr < RB1; rr++) {
                float4 x = ((const float4*)sx[rr])[qbase + u];   // warp-uniform -> broadcast
                acc[rr] = fmaf(x.x, w.x, acc[rr]);
                acc[rr] = fmaf(x.y, w.y, acc[rr]);
                acc[rr] = fmaf(x.z, w.z, acc[rr]);
                acc[rr] = fmaf(x.w, w.w, acc[rr]);
            }
        }
#pragma unroll
        for (int rr = 0; rr < RB1; rr++) {
            float v = acc[rr] + bias;
            int r = r0 + rr;
            if (is_w) slog[rr][j] = v;
            else if (is_e) {
                float mk = (mask[r] == 1.0f) ? 1.f : 0.f;
                g_ea[(size_t)r*128 + (ecol >> 1)*4 + (ecol & 1)] = mk / (1.f + expf(-v));
            } else if (is_a) {
                float mk = (mask[r] == 1.0f) ? 1.f : 0.f;
                g_ea[(size_t)r*128 + (acol >> 1)*4 + 2 + (acol & 1)] = mk * tanhf(v);
            }
        }
        __syncthreads();

        // softmax: warps cycle over 8 rows; writes permuted + padded (all 64 slots)
        for (int rr = wid; rr < RB1; rr += 6) {
            size_t base = (size_t)(r0 + rr) * 64;
            float v0 = slog[rr][lane];
            float v1 = (lane < 18) ? slog[rr][lane + 32] : -1e30f;
            float mx = fmaxf(v0, v1);
#pragma unroll
            for (int o = 16; o; o >>= 1) mx = fmaxf(mx, __shfl_xor_sync(0xffffffffu, mx, o));
            float e0 = expf(v0 - mx);
            float e1 = (lane < 18) ? expf(v1 - mx) : 0.f;
            float sm = e0 + e1;
#pragma unroll
            for (int o = 16; o; o >>= 1) sm += __shfl_xor_sync(0xffffffffu, sm, o);
            float inv = 1.f / sm;
            int m0 = lane, m1 = lane + 32;
            g_w[base + ((m0 & 7)*8 + (m0 >> 3))] = e0 * inv;
            g_w[base + ((m1 & 7)*8 + (m1 >> 3))] = (lane < 18) ? e1 * inv : 0.f;
        }
        __syncthreads();
    }
}

// ---------------- K2a: per-chunk composed linear-recurrence coefficients ----
// block = (b, chunk). 256 threads = 32 d-pairs x 8 m-parts. 3 LDG.128 per step.
__global__ __launch_bounds__(256) void k2a() {
    int blk = blockIdx.x;
    int b = blk >> 4, c = blk & (NCH-1);
    int tid = threadIdx.x;
    int dp = tid >> 3, mp = tid & 7;

    const float* wb = g_w + ((size_t)b*TT + c*CHL)*64 + mp*8;
    const float4* eap = (const float4*)g_ea + ((size_t)b*TT + c*CHL)*32 + dp;

    float U0[7], U1[7], C0[7], C1[7];
#pragma unroll
    for (int jj = 0; jj < 7; jj++) { U0[jj]=1.f; U1[jj]=1.f; C0[jj]=0.f; C1[jj]=0.f; }

#pragma unroll 4
    for (int s = 0; s < CHL; s++) {
        float4 wlo = *(const float4*)(wb + s*64);
        float4 whi = *(const float4*)(wb + s*64 + 4);
        float w[7] = {wlo.x, wlo.y, wlo.z, wlo.w, whi.x, whi.y, whi.z};
        float4 ea = eap[s*32];     // (e0, e1, a0, a1)
#pragma unroll
        for (int jj = 0; jj < 7; jj++) {
            float u0 = fmaf(-w[jj], ea.x, 1.f);
            float u1 = fmaf(-w[jj], ea.y, 1.f);
            U0[jj] *= u0;  U1[jj] *= u1;
            C0[jj] = fmaf(C0[jj], u0, w[jj]*ea.z);
            C1[jj] = fmaf(C1[jj], u1, w[jj]*ea.w);
        }
    }
    size_t off = (size_t)(b*NCH + c) * MD;
#pragma unroll
    for (int jj = 0; jj < 7; jj++) {
        int m = 8*jj + mp;
        if (m < MM) {
            float4 v = make_float4(U0[jj], C0[jj], U1[jj], C1[jj]);
            *(float4*)(g_UC + (off + (size_t)m*DD + dp*2)*2) = v;
        }
    }
}

// ---------------- K2b: compose chunk aggregates -> chunk start states -------
// thread = (b, d-pair within md space); float4 UC load, float2 mvstart store.
__global__ __launch_bounds__(256) void k2b(const float* __restrict__ Mv0) {
    int idx = blockIdx.x * blockDim.x + threadIdx.x;   // 0 .. BB*MD/2-1
    if (idx >= BB*(MD/2)) return;
    int b = idx / (MD/2), p = idx % (MD/2);
    float2 mv = ((const float2*)Mv0)[p];
#pragma unroll
    for (int c = 0; c < NCH; c++) {
        size_t off = (size_t)(b*NCH + c) * MD + 2*p;
        ((float2*)g_mvstart)[off >> 1] = mv;
        float4 uc = *(const float4*)(g_UC + off*2);    // (U0,C0,U1,C1)
        mv.x = fmaf(mv.x, uc.x, uc.y);
        mv.y = fmaf(mv.y, uc.z, uc.w);
    }
}

// ---------------- K2c: replay chunks, emit read vectors ---------------------
__global__ __launch_bounds__(256) void k2c() {
    int blk = blockIdx.x;
    int b = blk >> 4, c = blk & (NCH-1);
    int tid = threadIdx.x;
    int dp = tid >> 3, mp = tid & 7;

    const float* wb = g_w + ((size_t)b*TT + c*CHL)*64 + mp*8;
    const float4* eap = (const float4*)g_ea + ((size_t)b*TT + c*CHL)*32 + dp;
    float* rb = g_read + (size_t)b*(TT-1)*DD;

    size_t soff = (size_t)(b*NCH + c) * MD;
    float mv0[7], mv1[7];
#pragma unroll
    for (int jj = 0; jj < 7; jj++) {
        int m = 8*jj + mp;
        if (m < MM) {
            float2 s = *(const float2*)(g_mvstart + soff + (size_t)m*DD + dp*2);
            mv0[jj] = s.x; mv1[jj] = s.y;
        } else { mv0[jj] = 0.f; mv1[jj] = 0.f; }
    }

#pragma unroll 2
    for (int s = 0; s < CHL; s++) {
        int t = c*CHL + s;
        float4 wlo = *(const float4*)(wb + s*64);
        float4 whi = *(const float4*)(wb + s*64 + 4);
        float w[7] = {wlo.x, wlo.y, wlo.z, wlo.w, whi.x, whi.y, whi.z};
        float4 ea = eap[s*32];

        if (t > 0) {   // read with w_t against state after t-1
            float r0 = 0.f, r1 = 0.f;
#pragma unroll
            for (int jj = 0; jj < 7; jj++) {
                r0 = fmaf(w[jj], mv0[jj], r0);
                r1 = fmaf(w[jj], mv1[jj], r1);
            }
            r0 += __shfl_down_sync(0xffffffffu, r0, 4, 8);
            r0 += __shfl_down_sync(0xffffffffu, r0, 2, 8);
            r0 += __shfl_down_sync(0xffffffffu, r0, 1, 8);
            r1 += __shfl_down_sync(0xffffffffu, r1, 4, 8);
            r1 += __shfl_down_sync(0xffffffffu, r1, 2, 8);
            r1 += __shfl_down_sync(0xffffffffu, r1, 1, 8);
            if (mp == 0)
                *(float2*)(rb + (size_t)(t-1)*DD + dp*2) = make_float2(r0, r1);
        }
#pragma unroll
        for (int jj = 0; jj < 7; jj++) {
            float u0 = fmaf(-w[jj], ea.x, 1.f);
            float u1 = fmaf(-w[jj], ea.y, 1.f);
            mv0[jj] = fmaf(mv0[jj], u0, w[jj]*ea.z);
            mv1[jj] = fmaf(mv1[jj], u1, w[jj]*ea.w);
        }
    }
}

// ---------------- K3: f = tanh([read,k] @ f_W + f_b); p = f @ p_W + p_b -----
// 128 threads: j = tid>>1, s = tid&1 (i-half). 64 weights in registers.
#define RB3 8
__global__ __launch_bounds__(128) void k3_out(
    const int* __restrict__ question, const float* __restrict__ k_emb,
    const float* __restrict__ f_b, const float* __restrict__ p_W,
    const float* __restrict__ p_b, float* __restrict__ out) {
    __shared__ __align__(16) float sc[RB3][128];   // [read(64) | k(64)]
    __shared__ float warp_ps[4][RB3];
    int tid = threadIdx.x;
    int j = tid >> 1, s = tid & 1;
    int lane = tid & 31, wid = tid >> 5;

    float4 wq[16];
    const float4* W4 = (const float4*)(g_fWt + j*128 + s*64);
#pragma unroll
    for (int u = 0; u < 16; u++) wq[u] = W4[u];
    float fb = f_b[j], pw = p_W[j];
    float pbv = p_b[0];
    int qbase = s*16;

    for (int r0 = blockIdx.x*RB3; r0 < NROWS_OUT; r0 += gridDim.x*RB3) {
        for (int i = tid; i < RB3*32; i += 128) {
            int rr = i >> 5, q4 = i & 31;
            int r = r0 + rr;
            if (r < NROWS_OUT) {
                if (q4 < 16) ((float4*)sc[rr])[q4] = ((const float4*)g_read)[(size_t)r*16 + q4];
                else {
                    int bb = r / (TT-1), ttt = r - bb*(TT-1);
                    int q = question[bb*TT + ttt + 1];
                    ((float4*)sc[rr])[q4] = ((const float4*)k_emb)[q*16 + (q4 - 16)];
                }
            }
        }
        __syncthreads();

        float acc[RB3];
#pragma unroll
        for (int rr = 0; rr < RB3; rr++) acc[rr] = 0.f;
#pragma unroll
        for (int u = 0; u < 16; u++) {
            float4 w = wq[u];
#pragma unroll
            for (int rr = 0; rr < RB3; rr++) {
                float4 x = ((const float4*)sc[rr])[qbase + u];
                acc[rr] = fmaf(x.x, w.x, acc[rr]);
                acc[rr] = fmaf(x.y, w.y, acc[rr]);
                acc[rr] = fmaf(x.z, w.z, acc[rr]);
                acc[rr] = fmaf(x.w, w.w, acc[rr]);
            }
        }
#pragma unroll
        for (int rr = 0; rr < RB3; rr++) {
            float a2 = acc[rr] + __shfl_down_sync(0xffffffffu, acc[rr], 1, 2);
            float pv = (s == 0) ? tanhf(a2 + fb) * pw : 0.f;
#pragma unroll
            for (int o = 16; o; o >>= 1) pv += __shfl_xor_sync(0xffffffffu, pv, o);
            if (lane == 0) warp_ps[wid][rr] = pv;
        }
        __syncthreads();
        if (tid < RB3) {
            int r = r0 + tid;
            if (r < NROWS_OUT) {
                float sum = pbv;
#pragma unroll
                for (int wgi = 0; wgi < 4; wgi++) sum += warp_ps[wgi][tid];
                out[r] = sum;
            }
        }
        __syncthreads();
    }
}

// ---------------- launch ----------------------------------------------------
extern "C" void kernel_launch(void* const* d_in, const int* in_sizes, int n_in,
                              void* d_out, int out_size) {
    const int*   question = (const int*)  d_in[0];
    const int*   response = (const int*)  d_in[1];
    const float* mask     = (const float*)d_in[2];
    const float* k_emb    = (const float*)d_in[3];
    const float* v_emb    = (const float*)d_in[4];
    const float* Mk       = (const float*)d_in[5];
    const float* Mv0      = (const float*)d_in[6];
    const float* e_W      = (const float*)d_in[7];
    const float* e_b      = (const float*)d_in[8];
    const float* a_W      = (const float*)d_in[9];
    const float* a_b      = (const float*)d_in[10];
    const float* f_W      = (const float*)d_in[11];
    const float* f_b      = (const float*)d_in[12];
    const float* p_W      = (const float*)d_in[13];
    const float* p_b      = (const float*)d_in[14];
    float* out = (float*)d_out;

    k0_prep<<<64, 256>>>(Mk, e_W, a_W, e_b, a_b, f_W);
    k1_wea<<<1024, 192>>>(question, response, mask, k_emb, v_emb);
    k2a<<<BB*NCH, 256>>>();
    k2b<<<(BB*(MD/2) + 255)/256, 256>>>(Mv0);
    k2c<<<BB*NCH, 256>>>();
    k3_out<<<1024, 128>>>(question, k_emb, f_b, p_W, p_b, out);
}